// round 14
// baseline (speedup 1.0000x reference)
#include <cuda_runtime.h>
#include <cstdint>

// SyntheticTripletLoss closed form: per valid row only
//   pp=<p,p>, tt=<t,t>, pt=<p,t>
//   sim_pn = (pp - pt^2) / max(sqrt(pp - 2pt^2 + pt^2*tt), EPS)
//   loss   = max(MARGIN + sim_pn - pt, 0); mean over valid rows.
//
// R14 = R13 (single packed-u64 atomic tail: bits[50:61] completion count,
// bits[0:50] loss in 2^24 fixed point; exact+commutative -> deterministic)
// + R12 (512-thread blocks): 1024 blocks -> half the atomics, half the
// block prologues. Streaming body unchanged (at the LTS cycle floor).

#define MARGIN 0.5f
#define EPS_N 1e-12f

static constexpr int B = 32;
static constexpr int T = 512;
static constexpr int D = 512;
static constexpr int WARPS_PER_BLOCK = 16;
static constexpr int THREADS = WARPS_PER_BLOCK * 32;    // 512
static constexpr int ROWS = B * T;                      // 16384
static constexpr int NBLOCKS = ROWS / WARPS_PER_BLOCK;  // 1024

static constexpr double FIX_SCALE = 16777216.0;         // 2^24
static constexpr int CNT_SHIFT = 50;

__device__ unsigned long long g_acc;   // zero-init; last block resets each run

__global__ __launch_bounds__(THREADS)
void triplet_atomic512_kernel(const float* __restrict__ preds,
                              const float* __restrict__ targets,
                              const int* __restrict__ lengths,
                              float* __restrict__ out) {
    const int warp = threadIdx.x >> 5;
    const int lane = threadIdx.x & 31;
    const int row  = blockIdx.x * WARPS_PER_BLOCK + warp;
    const int b    = row >> 9;        // row / T
    const int t    = row & (T - 1);   // row % T

    float loss = 0.0f;

    if (t < __ldg(&lengths[b])) {
        const float4* __restrict__ p4 =
            reinterpret_cast<const float4*>(preds + (size_t)row * D);
        const float4* __restrict__ t4 =
            reinterpret_cast<const float4*>(targets + (size_t)row * D);

        // 512 floats / 32 lanes = 4 float4 per lane per tensor; front-batch
        // all 8 loads for MLP.
        float4 a0 = __ldg(p4 + lane);
        float4 a1 = __ldg(p4 + lane + 32);
        float4 a2 = __ldg(p4 + lane + 64);
        float4 a3 = __ldg(p4 + lane + 96);
        float4 c0 = __ldg(t4 + lane);
        float4 c1 = __ldg(t4 + lane + 32);
        float4 c2 = __ldg(t4 + lane + 64);
        float4 c3 = __ldg(t4 + lane + 96);

        float pp = 0.f, tt = 0.f, pt = 0.f;
        #define ACC(a, c)                                                        \
            pp = fmaf(a.x, a.x, fmaf(a.y, a.y, fmaf(a.z, a.z, fmaf(a.w, a.w, pp)))); \
            tt = fmaf(c.x, c.x, fmaf(c.y, c.y, fmaf(c.z, c.z, fmaf(c.w, c.w, tt)))); \
            pt = fmaf(a.x, c.x, fmaf(a.y, c.y, fmaf(a.z, c.z, fmaf(a.w, c.w, pt))));
        ACC(a0, c0) ACC(a1, c1) ACC(a2, c2) ACC(a3, c3)
        #undef ACC

        #pragma unroll
        for (int off = 16; off; off >>= 1) {
            pp += __shfl_xor_sync(0xffffffffu, pp, off);
            tt += __shfl_xor_sync(0xffffffffu, tt, off);
            pt += __shfl_xor_sync(0xffffffffu, pt, off);
        }

        float pt2  = pt * pt;
        float n2   = fmaxf(pp - 2.0f * pt2 + pt2 * tt, 0.0f);
        float norm = fmaxf(sqrtf(n2), EPS_N);
        loss = fmaxf(MARGIN + (pp - pt2) / norm - pt, 0.0f);
    }

    // ---- block sum (smem) -> single packed atomic ----
    __shared__ float s_warp[WARPS_PER_BLOCK];
    if (lane == 0) s_warp[warp] = loss;
    __syncthreads();

    if (threadIdx.x == 0) {
        float sum = 0.f;
        #pragma unroll
        for (int i = 0; i < WARPS_PER_BLOCK; i++) sum += s_warp[i];

        // 2^24 fixed point via double (exact in this range); loss >= 0.
        // Overflow audit: block sum <= ~2e3 -> <=2^35 fixed; 1024 blocks
        // -> <=2^45 < 2^50. Count: 1024 * 2^50 = 2^60 < 2^64.
        unsigned long long contrib =
            (unsigned long long)((double)sum * FIX_SCALE);
        unsigned long long packed = (1ULL << CNT_SHIFT) + contrib;

        unsigned long long old = atomicAdd(&g_acc, packed);

        if ((old >> CNT_SHIFT) == (unsigned long long)(NBLOCKS - 1)) {
            // Last block: chip total is in the atomic's return value.
            unsigned long long total_fix =
                (old + packed) & ((1ULL << CNT_SHIFT) - 1ULL);
            int cnt = 0;
            #pragma unroll
            for (int i = 0; i < B; i++) cnt += __ldg(&lengths[i]);
            out[0] = (float)((double)total_fix / FIX_SCALE / (double)cnt);
            g_acc = 0;   // reset for next graph replay (all other blocks'
                         // atomics preceded ours; no later readers)
        }
    }
}

extern "C" void kernel_launch(void* const* d_in, const int* in_sizes, int n_in,
                              void* d_out, int out_size) {
    const float* preds   = (const float*)d_in[0];
    const float* targets = (const float*)d_in[1];
    const int*   lengths = (const int*)d_in[2];
    float* out = (float*)d_out;

    triplet_atomic512_kernel<<<NBLOCKS, THREADS>>>(preds, targets, lengths, out);
}

// round 15
// speedup vs baseline: 1.1875x; 1.1875x over previous
#include <cuda_runtime.h>
#include <cstdint>

// SyntheticTripletLoss closed form: per valid row only
//   pp=<p,p>, tt=<t,t>, pt=<p,t>
//   sim_pn = (pp - pt^2) / max(sqrt(pp - 2pt^2 + pt^2*tt), EPS)
//   loss   = max(MARGIN + sim_pn - pt, 0); mean over valid rows.
//
// R15 = R9 (balanced: prefix-scan of lengths + binary search; warps map only
// to valid rows, so all memory work compacts into the first ~total/8 blocks)
// + R13 (single packed-u64 atomic tail: bits[50:61] completion count,
// bits[0:50] loss in 2^24 fixed point; integer adds are exact+commutative ->
// deterministic; last block gets the chip total in the atomic return value).

#define MARGIN 0.5f
#define EPS_N 1e-12f

static constexpr int B = 32;
static constexpr int T = 512;
static constexpr int D = 512;
static constexpr int WARPS_PER_BLOCK = 8;
static constexpr int THREADS = WARPS_PER_BLOCK * 32;    // 256
static constexpr int ROWS = B * T;                      // 16384
static constexpr int NBLOCKS = ROWS / WARPS_PER_BLOCK;  // 2048 (worst case)

static constexpr double FIX_SCALE = 16777216.0;         // 2^24
static constexpr int CNT_SHIFT = 50;

__device__ unsigned long long g_acc;   // zero-init; last block resets each run

__global__ __launch_bounds__(THREADS)
void triplet_final_kernel(const float* __restrict__ preds,
                          const float* __restrict__ targets,
                          const int* __restrict__ lengths,
                          float* __restrict__ out) {
    __shared__ int   s_pre[B + 1];            // exclusive prefix of lengths
    __shared__ float s_warp[WARPS_PER_BLOCK];

    const int warp = threadIdx.x >> 5;
    const int lane = threadIdx.x & 31;

    // Warp 0: inclusive shuffle-scan of lengths[0..31] -> prefix in smem.
    if (warp == 0) {
        int v = __ldg(&lengths[lane]);
        int s = v;
        #pragma unroll
        for (int off = 1; off < 32; off <<= 1) {
            int n = __shfl_up_sync(0xffffffffu, s, off);
            if (lane >= off) s += n;
        }
        s_pre[lane + 1] = s;
        if (lane == 0) s_pre[0] = 0;
    }
    __syncthreads();

    const int total = s_pre[B];       // number of valid rows
    const int vid   = blockIdx.x * WARPS_PER_BLOCK + warp;

    float loss = 0.0f;

    if (vid < total) {
        // binary search: largest b with s_pre[b] <= vid
        int lo = 0, hi = B;
        #pragma unroll
        for (int i = 0; i < 5; i++) {         // log2(32)
            int mid = (lo + hi) >> 1;
            if (s_pre[mid] <= vid) lo = mid; else hi = mid;
        }
        const int row = lo * T + (vid - s_pre[lo]);

        const float4* __restrict__ p4 =
            reinterpret_cast<const float4*>(preds + (size_t)row * D);
        const float4* __restrict__ t4 =
            reinterpret_cast<const float4*>(targets + (size_t)row * D);

        // 512 floats / 32 lanes = 4 float4 per lane per tensor; front-batch
        // all 8 loads for MLP.
        float4 a0 = __ldg(p4 + lane);
        float4 a1 = __ldg(p4 + lane + 32);
        float4 a2 = __ldg(p4 + lane + 64);
        float4 a3 = __ldg(p4 + lane + 96);
        float4 c0 = __ldg(t4 + lane);
        float4 c1 = __ldg(t4 + lane + 32);
        float4 c2 = __ldg(t4 + lane + 64);
        float4 c3 = __ldg(t4 + lane + 96);

        float pp = 0.f, tt = 0.f, pt = 0.f;
        #define ACC(a, c)                                                        \
            pp = fmaf(a.x, a.x, fmaf(a.y, a.y, fmaf(a.z, a.z, fmaf(a.w, a.w, pp)))); \
            tt = fmaf(c.x, c.x, fmaf(c.y, c.y, fmaf(c.z, c.z, fmaf(c.w, c.w, tt)))); \
            pt = fmaf(a.x, c.x, fmaf(a.y, c.y, fmaf(a.z, c.z, fmaf(a.w, c.w, pt))));
        ACC(a0, c0) ACC(a1, c1) ACC(a2, c2) ACC(a3, c3)
        #undef ACC

        #pragma unroll
        for (int off = 16; off; off >>= 1) {
            pp += __shfl_xor_sync(0xffffffffu, pp, off);
            tt += __shfl_xor_sync(0xffffffffu, tt, off);
            pt += __shfl_xor_sync(0xffffffffu, pt, off);
        }

        float pt2  = pt * pt;
        float n2   = fmaxf(pp - 2.0f * pt2 + pt2 * tt, 0.0f);
        float norm = fmaxf(sqrtf(n2), EPS_N);
        loss = fmaxf(MARGIN + (pp - pt2) / norm - pt, 0.0f);
    }

    // ---- block sum (smem) -> single packed atomic ----
    if (lane == 0) s_warp[warp] = loss;
    __syncthreads();

    if (threadIdx.x == 0) {
        float sum = 0.f;
        #pragma unroll
        for (int i = 0; i < WARPS_PER_BLOCK; i++) sum += s_warp[i];

        // 2^24 fixed point via double (exact in this range); loss >= 0.
        // Overflow audit: block sum <= ~1e3 -> <=2^34 fixed; 2048 blocks
        // -> <=2^45 < 2^50. Count: 2048 * 2^50 = 2^61 < 2^64.
        unsigned long long contrib =
            (unsigned long long)((double)sum * FIX_SCALE);
        unsigned long long packed = (1ULL << CNT_SHIFT) + contrib;

        unsigned long long old = atomicAdd(&g_acc, packed);

        if ((old >> CNT_SHIFT) == (unsigned long long)(NBLOCKS - 1)) {
            // Last block: chip total is in the atomic's return value.
            unsigned long long total_fix =
                (old + packed) & ((1ULL << CNT_SHIFT) - 1ULL);
            out[0] = (float)((double)total_fix / FIX_SCALE / (double)total);
            g_acc = 0;   // reset for next graph replay (all other blocks'
                         // atomics preceded ours; no later readers)
        }
    }
}

extern "C" void kernel_launch(void* const* d_in, const int* in_sizes, int n_in,
                              void* d_out, int out_size) {
    const float* preds   = (const float*)d_in[0];
    const float* targets = (const float*)d_in[1];
    const int*   lengths = (const int*)d_in[2];
    float* out = (float*)d_out;

    triplet_final_kernel<<<NBLOCKS, THREADS>>>(preds, targets, lengths, out);
}

// round 16
// speedup vs baseline: 1.2214x; 1.0286x over previous
#include <cuda_runtime.h>
#include <cstdint>

// SyntheticTripletLoss closed form: per valid row only
//   pp=<p,p>, tt=<t,t>, pt=<p,t>
//   sim_pn = (pp - pt^2) / max(sqrt(pp - 2pt^2 + pt^2*tt), EPS)
//   loss   = max(MARGIN + sim_pn - pt, 0); mean over valid rows.
//
// R16 = R15 with a register-only row mapper: each warp privately loads
// lengths[lane], shuffle-scans, and resolves (b, t) for its valid-row id via
// ballot+clz+shuffle -- no smem scan, no __syncthreads before the streaming
// loads. Tail unchanged: one packed-u64 atomic per block (count in bits
// [50:61], loss in 2^24 fixed point in bits [0:50]); exact + commutative ->
// deterministic; last block finishes from the atomic's return value.

#define MARGIN 0.5f
#define EPS_N 1e-12f

static constexpr int B = 32;
static constexpr int T = 512;
static constexpr int D = 512;
static constexpr int WARPS_PER_BLOCK = 8;
static constexpr int THREADS = WARPS_PER_BLOCK * 32;    // 256
static constexpr int ROWS = B * T;                      // 16384
static constexpr int NBLOCKS = ROWS / WARPS_PER_BLOCK;  // 2048 (worst case)

static constexpr double FIX_SCALE = 16777216.0;         // 2^24
static constexpr int CNT_SHIFT = 50;

__device__ unsigned long long g_acc;   // zero-init; last block resets each run

__global__ __launch_bounds__(THREADS)
void triplet_reg_kernel(const float* __restrict__ preds,
                        const float* __restrict__ targets,
                        const int* __restrict__ lengths,
                        float* __restrict__ out) {
    const int warp = threadIdx.x >> 5;
    const int lane = threadIdx.x & 31;

    // ---- warp-private scan of lengths (register-only, no smem/sync) ----
    const int len = __ldg(&lengths[lane]);   // L2-hot after first wave
    int inc = len;
    #pragma unroll
    for (int off = 1; off < 32; off <<= 1) {
        int n = __shfl_up_sync(0xffffffffu, inc, off);
        if (lane >= off) inc += n;
    }
    const int total = __shfl_sync(0xffffffffu, inc, 31);
    const int excl  = inc - len;             // exclusive prefix at this lane

    const int vid = blockIdx.x * WARPS_PER_BLOCK + warp;

    float loss = 0.0f;

    if (vid < total) {
        // Find batch b = largest lane with excl[lane] <= vid (excl is
        // nondecreasing): ballot + clz, then fetch excl[b] via shuffle.
        unsigned int mask = __ballot_sync(0xffffffffu, excl <= vid);
        const int bsel = 31 - __clz(mask);
        const int base = __shfl_sync(0xffffffffu, excl, bsel);
        const int row  = bsel * T + (vid - base);

        const float4* __restrict__ p4 =
            reinterpret_cast<const float4*>(preds + (size_t)row * D);
        const float4* __restrict__ t4 =
            reinterpret_cast<const float4*>(targets + (size_t)row * D);

        // 512 floats / 32 lanes = 4 float4 per lane per tensor; front-batch
        // all 8 loads for MLP.
        float4 a0 = __ldg(p4 + lane);
        float4 a1 = __ldg(p4 + lane + 32);
        float4 a2 = __ldg(p4 + lane + 64);
        float4 a3 = __ldg(p4 + lane + 96);
        float4 c0 = __ldg(t4 + lane);
        float4 c1 = __ldg(t4 + lane + 32);
        float4 c2 = __ldg(t4 + lane + 64);
        float4 c3 = __ldg(t4 + lane + 96);

        float pp = 0.f, tt = 0.f, pt = 0.f;
        #define ACC(a, c)                                                        \
            pp = fmaf(a.x, a.x, fmaf(a.y, a.y, fmaf(a.z, a.z, fmaf(a.w, a.w, pp)))); \
            tt = fmaf(c.x, c.x, fmaf(c.y, c.y, fmaf(c.z, c.z, fmaf(c.w, c.w, tt)))); \
            pt = fmaf(a.x, c.x, fmaf(a.y, c.y, fmaf(a.z, c.z, fmaf(a.w, c.w, pt))));
        ACC(a0, c0) ACC(a1, c1) ACC(a2, c2) ACC(a3, c3)
        #undef ACC

        #pragma unroll
        for (int off = 16; off; off >>= 1) {
            pp += __shfl_xor_sync(0xffffffffu, pp, off);
            tt += __shfl_xor_sync(0xffffffffu, tt, off);
            pt += __shfl_xor_sync(0xffffffffu, pt, off);
        }

        float pt2  = pt * pt;
        float n2   = fmaxf(pp - 2.0f * pt2 + pt2 * tt, 0.0f);
        float norm = fmaxf(sqrtf(n2), EPS_N);
        loss = fmaxf(MARGIN + (pp - pt2) / norm - pt, 0.0f);
    }

    // ---- block sum (smem) -> single packed atomic ----
    __shared__ float s_warp[WARPS_PER_BLOCK];
    if (lane == 0) s_warp[warp] = loss;
    __syncthreads();

    if (threadIdx.x == 0) {
        float sum = 0.f;
        #pragma unroll
        for (int i = 0; i < WARPS_PER_BLOCK; i++) sum += s_warp[i];

        // 2^24 fixed point via double (exact in this range); loss >= 0.
        // Overflow audit: block sum <= ~1e3 -> <=2^34 fixed; 2048 blocks
        // -> <=2^45 < 2^50. Count: 2048 * 2^50 = 2^61 < 2^64.
        unsigned long long contrib =
            (unsigned long long)((double)sum * FIX_SCALE);
        unsigned long long packed = (1ULL << CNT_SHIFT) + contrib;

        unsigned long long old = atomicAdd(&g_acc, packed);

        if ((old >> CNT_SHIFT) == (unsigned long long)(NBLOCKS - 1)) {
            // Last block: chip total is in the atomic's return value.
            unsigned long long total_fix =
                (old + packed) & ((1ULL << CNT_SHIFT) - 1ULL);
            out[0] = (float)((double)total_fix / FIX_SCALE / (double)total);
            g_acc = 0;   // reset for next graph replay (all other blocks'
                         // atomics preceded ours; no later readers)
        }
    }
}

extern "C" void kernel_launch(void* const* d_in, const int* in_sizes, int n_in,
                              void* d_out, int out_size) {
    const float* preds   = (const float*)d_in[0];
    const float* targets = (const float*)d_in[1];
    const int*   lengths = (const int*)d_in[2];
    float* out = (float*)d_out;

    triplet_reg_kernel<<<NBLOCKS, THREADS>>>(preds, targets, lengths, out);
}